// round 11
// baseline (speedup 1.0000x reference)
#include <cuda_runtime.h>
#include <cstdint>

// Problem constants (fixed by the dataset)
#define NWORDS 100000
#define SHEADS 64
#define QB     50
#define TILE   64
#define NTILES ((NWORDS + TILE - 1) / TILE)   // 1563 (last tile: 32 rows)
#define GRIDX  152
#define NTHR   256

typedef unsigned long long ull;

// ---- packed f32x2 ops (sm_103a) ----
// f32x2 = 2 fp32 lanes per instr at rt~4/SMSP (saves issue slots, not FLOPs).
// NUMERICS (R9 post-mortem): keep the all-positive 3-product dot. The
// h2-elimination rewrite (p2 + (p0-p2)h0 + (p1-p2)h1) cancels catastrophically
// when dot << p2, and those tiny-cov words dominate sum(c^2/cov). rel_err 2e-2.
#define FMA2(d,a,b,c) asm("fma.rn.f32x2 %0, %1, %2, %3;" : "=l"(d) : "l"(a), "l"(b), "l"(c))
#define MUL2(d,a,b)   asm("mul.rn.f32x2 %0, %1, %2;"     : "=l"(d) : "l"(a), "l"(b))
#define PACK2(d,lo,hi)   asm("mov.b64 %0, {%1, %2};" : "=l"(d) : "f"(lo), "f"(hi))
#define UNPACK2(lo,hi,s) asm("mov.b64 {%0, %1}, %2;" : "=f"(lo), "=f"(hi) : "l"(s))

__device__ double g_part[NTILES];
__device__ int    g_ticket = GRIDX;   // reset by the last block each run
__device__ int    g_done   = 0;

// 16B async copy, L1-bypass (no reuse of pauli data)
__device__ __forceinline__ void cp_async16(float* smem_dst, const float* gsrc) {
    uint32_t s = (uint32_t)__cvta_generic_to_shared(smem_dst);
    asm volatile("cp.async.cg.shared.global [%0], [%1], 16;" :: "r"(s), "l"(gsrc));
}
__device__ __forceinline__ void cp_commit()   { asm volatile("cp.async.commit_group;"); }
__device__ __forceinline__ void cp_wait_all() { asm volatile("cp.async.wait_all;"); }

// Branch-free softplus(20x): max(z,0) + log1p(exp(-|z|)); log1pf keeps accuracy
// for tiny exp(-|z|) so small heads survive normalization.
__device__ __forceinline__ float softplus20(float x) {
    float z = 20.0f * x;
    return fmaxf(z, 0.0f) + log1pf(__expf(-fabsf(z)));
}

// Dynamic smem layout (floats):
//   buf0   : TILE*150 =  9600
//   buf1   : TILE*150 =  9600
//   sm_h0  : QB*64    =  3200   (SoA per-p, pair-interleaved:
//   sm_h1  : QB*64    =  3200    idx = q*64 + pair*2 + (s&1))
//   sm_h2  : QB*64    =  3200
//   sm_hr  : 64
//   sm_w   : 4*TILE   = 256     (cross-quarter coverage combine)
// total = 29120 floats = 116480 B  (1 CTA/SM)
#define SMEM_FLOATS (2*TILE*150 + 3*QB*64 + SHEADS + 4*TILE)

__global__ void __launch_bounds__(NTHR, 1)
main_kernel(const float* __restrict__ pauli,        // [N,150]
            const float* __restrict__ coeff,        // [N]
            const float* __restrict__ heads_param,  // [S,Q,3]
            const float* __restrict__ hr_param,     // [S]
            float* __restrict__ out) {
    extern __shared__ float sm[];
    float* buf[2];
    buf[0]       = sm;
    buf[1]       = sm + TILE * 150;
    float* sm_h0 = sm + 2 * TILE * 150;
    float* sm_h1 = sm_h0 + QB * 64;
    float* sm_h2 = sm_h1 + QB * 64;
    float* sm_hr = sm_h2 + QB * 64;
    float* sm_w  = sm_hr + SHEADS;
    __shared__ float  warpsum[8];
    __shared__ float  s_hrtmp[SHEADS];
    __shared__ float  s_hrsum;
    __shared__ int    s_nxt;          // block-uniform next ticket
    __shared__ int    s_last;         // last block to finish?
    __shared__ double red[NTHR];      // final-reduction scratch

    const int tid     = threadIdx.x;
    const int quarter = tid >> 6;     // 0..3: owns head pairs [quarter*8, quarter*8+8)
    const int word    = tid & 63;

    // ---- kick off prefetch of this block's first tile ----
    int cur = blockIdx.x;             // GRIDX <= NTILES, always valid here
    {
        const int rows = min(TILE, NWORDS - cur * TILE);
        const int n16  = rows * 150 / 4;              // rows multiple of 32
        const float* src = pauli + (size_t)cur * TILE * 150;
        for (int i = tid; i < n16; i += NTHR)
            cp_async16(buf[0] + i * 4, src + i * 4);
        cp_commit();
    }

    // ---- head prep, once per block, overlapped with the cp.async in flight ----
    for (int i = tid; i < SHEADS * QB; i += NTHR) {
        const int s = i / QB;
        const int q = i - s * QB;
        const float* hp = heads_param + i * 3;        // i == s*QB + q
        float a = softplus20(hp[0]);
        float b = softplus20(hp[1]);
        float c = softplus20(hp[2]);
        float inv = 1.0f / fmaxf(a + b + c, 1e-12f);
        const int idx = q * 64 + (s >> 1) * 2 + (s & 1);
        sm_h0[idx] = a * inv;
        sm_h1[idx] = b * inv;
        sm_h2[idx] = c * inv;
    }
    if (tid < SHEADS) s_hrtmp[tid] = softplus20(hr_param[tid]);
    __syncthreads();
    if (tid < 32) {
        float v = s_hrtmp[tid] + s_hrtmp[tid + 32];
        #pragma unroll
        for (int off = 16; off; off >>= 1)
            v += __shfl_down_sync(0xffffffffu, v, off);
        if (tid == 0) s_hrsum = fmaxf(v, 1e-12f);
    }
    __syncthreads();
    if (tid < SHEADS)
        sm_hr[tid] = (s_hrtmp[tid] / s_hrsum + 0.001f / (float)SHEADS) / 1.001f;

    // block-uniform ticket fetch
    if (tid == 0) s_nxt = atomicAdd(&g_ticket, 1);

    int pb = 0;                       // buffer holding `cur`
    cp_wait_all();
    __syncthreads();                  // first tile + heads + hr + s_nxt ready

    while (cur < NTILES) {
        const int nxt = s_nxt;        // uniform (written before a prior barrier)

        // ---- prefetch the next tile into the other buffer ----
        if (nxt < NTILES) {
            const int rows_n = min(TILE, NWORDS - nxt * TILE);
            const int n16    = rows_n * 150 / 4;
            const float* src = pauli + (size_t)nxt * TILE * 150;
            float* dst = buf[pb ^ 1];
            for (int i = tid; i < n16; i += NTHR)
                cp_async16(dst + i * 4, src + i * 4);
        }
        cp_commit();

        // ---- coverage: thread = (word, 8 head-pairs of its quarter) ----
        const int rows = min(TILE, NWORDS - cur * TILE);
        const float* row = buf[pb] + ((word < rows) ? word : 0) * 150;

        ull acc[8];
        ull one; PACK2(one, 1.0f, 1.0f);
        #pragma unroll
        for (int i = 0; i < 8; ++i) acc[i] = one;

        for (int q = 0; q < QB; ++q) {
            const float p0 = row[q * 3 + 0];
            const float p1 = row[q * 3 + 1];
            const float p2 = row[q * 3 + 2];
            ull p0x, p1x, p2x;
            PACK2(p0x, p0, p0); PACK2(p1x, p1, p1); PACK2(p2x, p2, p2);
            const ulonglong2* H0 = (const ulonglong2*)sm_h0 + q * 16 + quarter * 4;
            const ulonglong2* H1 = (const ulonglong2*)sm_h1 + q * 16 + quarter * 4;
            const ulonglong2* H2 = (const ulonglong2*)sm_h2 + q * 16 + quarter * 4;
            #pragma unroll
            for (int j = 0; j < 4; ++j) {
                ulonglong2 a0 = H0[j];   // broadcast LDS.128, conflict-free
                ulonglong2 a1 = H1[j];
                ulonglong2 a2 = H2[j];
                ull d0, d1;
                MUL2(d0, p2x, a2.x);
                FMA2(d0, p1x, a1.x, d0);
                FMA2(d0, p0x, a0.x, d0);
                MUL2(acc[2 * j + 0], acc[2 * j + 0], d0);
                MUL2(d1, p2x, a2.y);
                FMA2(d1, p1x, a1.y, d1);
                FMA2(d1, p0x, a0.y, d1);
                MUL2(acc[2 * j + 1], acc[2 * j + 1], d1);
            }
        }

        // ---- ratio-weighted sum over this quarter's 16 heads ----
        const ull* hrp = (const ull*)sm_hr + quarter * 8;
        ull w2; PACK2(w2, 0.0f, 0.0f);
        #pragma unroll
        for (int i = 0; i < 8; ++i) FMA2(w2, hrp[i], acc[i], w2);
        float wlo, whi; UNPACK2(wlo, whi, w2);
        const float wq = wlo + whi;

        if (quarter) sm_w[quarter * TILE + word] = wq;
        __syncthreads();                 // B1: separates s_nxt read / refill

        if (tid == 0 && nxt < NTILES) s_nxt = atomicAdd(&g_ticket, 1);

        float term = 0.0f;
        if (quarter == 0 && word < rows) {
            const float c = coeff[cur * TILE + word];
            const float w = wq + sm_w[TILE + word]
                          + sm_w[2 * TILE + word] + sm_w[3 * TILE + word];
            term = (c * c) / w;
        }
        // deterministic reduction (nonzero terms live in warps 0-1)
        #pragma unroll
        for (int off = 16; off; off >>= 1)
            term += __shfl_down_sync(0xffffffffu, term, off);
        if ((tid & 31) == 0) warpsum[tid >> 5] = term;
        __syncthreads();
        if (tid == 0) g_part[cur] = (double)warpsum[0] + (double)warpsum[1];

        cp_wait_all();
        __syncthreads();                 // B2: buffer ready, smem reusable
        cur = nxt;
        pb ^= 1;
    }

    // ---- fused final reduction: last block to finish sums g_part ----
    if (tid == 0) {
        __threadfence();                              // publish g_part writes
        s_last = (atomicAdd(&g_done, 1) == GRIDX - 1);
    }
    __syncthreads();
    if (s_last) {
        __threadfence();                              // acquire g_part writes
        double v = 0.0;
        #pragma unroll
        for (int k = 0; k < (NTILES + NTHR - 1) / NTHR; ++k) {
            int idx = tid + k * NTHR;
            if (idx < NTILES) v += g_part[idx];
        }
        red[tid] = v;
        __syncthreads();
        #pragma unroll
        for (int off = NTHR / 2; off; off >>= 1) {
            if (tid < off) red[tid] += red[tid + off];
            __syncthreads();
        }
        if (tid == 0) {
            out[0] = (float)red[0];
            g_ticket = GRIDX;   // reset scheduler state for the next replay
            g_done   = 0;
        }
    }
}

extern "C" void kernel_launch(void* const* d_in, const int* in_sizes, int n_in,
                              void* d_out, int out_size) {
    const float* pauli = (const float*)d_in[0];  // [N,Q,P]
    const float* coeff = (const float*)d_in[1];  // [N]
    const float* hp    = (const float*)d_in[2];  // [S,Q,P]
    const float* hrp   = (const float*)d_in[3];  // [S]
    float* out = (float*)d_out;

    const size_t smem = (size_t)SMEM_FLOATS * sizeof(float); // 116480 B
    cudaFuncSetAttribute(main_kernel, cudaFuncAttributeMaxDynamicSharedMemorySize, (int)smem);

    main_kernel<<<GRIDX, NTHR, smem>>>(pauli, coeff, hp, hrp, out);
}

// round 13
// speedup vs baseline: 1.1739x; 1.1739x over previous
#include <cuda_runtime.h>
#include <cstdint>

// Problem constants (fixed by the dataset)
#define NWORDS 100000
#define SHEADS 64
#define QB     50
#define TILE   128
#define RSTRIDE 150
#define NTILES ((NWORDS + TILE - 1) / TILE)   // 782 (last tile: 32 rows)
#define GRIDX  152
#define NTHR   256

typedef unsigned long long ull;

// ---- packed f32x2 ops (sm_103a) ----
// R11 calibration: f32x2 is FULL-RATE (rt2/SMSP, 2 FLOP lanes/instr) -> 2x FLOP
// throughput vs scalar FFMA. The binding pipe in R11 was the smem crossbar
// (L1=66%): broadcast LDS.128 ~2 wavefronts, conflicted scalar LDS ~2 wf.
// This version register-blocks 2 words x 8 pairs per thread to double fma work
// per LDS byte.
#define FMA2(d,a,b,c) asm("fma.rn.f32x2 %0, %1, %2, %3;" : "=l"(d) : "l"(a), "l"(b), "l"(c))
#define MUL2(d,a,b)   asm("mul.rn.f32x2 %0, %1, %2;"     : "=l"(d) : "l"(a), "l"(b))
#define PACK2(d,lo,hi)   asm("mov.b64 %0, {%1, %2};" : "=l"(d) : "f"(lo), "f"(hi))
#define UNPACK2(lo,hi,s) asm("mov.b64 {%0, %1}, %2;" : "=f"(lo), "=f"(hi) : "l"(s))

__device__ double g_part[NTILES];
__device__ int    g_ticket = GRIDX;   // reset by the last block each run
__device__ int    g_done   = 0;

// 16B async copy, L1-bypass (no reuse of pauli data)
__device__ __forceinline__ void cp_async16(float* smem_dst, const float* gsrc) {
    uint32_t s = (uint32_t)__cvta_generic_to_shared(smem_dst);
    asm volatile("cp.async.cg.shared.global [%0], [%1], 16;" :: "r"(s), "l"(gsrc));
}
__device__ __forceinline__ void cp_commit()   { asm volatile("cp.async.commit_group;"); }
__device__ __forceinline__ void cp_wait_all() { asm volatile("cp.async.wait_all;"); }

// Branch-free softplus(20x): max(z,0) + log1p(exp(-|z|)); log1pf keeps accuracy
// for tiny exp(-|z|) so small heads survive normalization.
// NUMERICS: the dot stays the all-positive 3-product form. h2-elimination
// rewrites cancel catastrophically for tiny-cov words (R9: rel_err 2e-2).
__device__ __forceinline__ float softplus20(float x) {
    float z = 20.0f * x;
    return fmaxf(z, 0.0f) + log1pf(__expf(-fabsf(z)));
}

// Dynamic smem layout (floats):
//   buf0   : TILE*150 = 19200
//   buf1   : TILE*150 = 19200
//   sm_h0  : QB*64    =  3200   (SoA per-p, pair-interleaved ull:
//   sm_h1  : QB*64    =  3200    ull idx = q*32 + pair, lo=even head, hi=odd)
//   sm_h2  : QB*64    =  3200
//   sm_hr  : 64
//   sm_w   : 3*TILE   = 384     (pg 1..3 publish per-word partial coverage)
// total = 48448 floats = 193792 B  (1 CTA/SM)
#define SMEM_FLOATS (2*TILE*RSTRIDE + 3*QB*64 + SHEADS + 3*TILE)

__global__ void __launch_bounds__(NTHR, 1)
main_kernel(const float* __restrict__ pauli,        // [N,150]
            const float* __restrict__ coeff,        // [N]
            const float* __restrict__ heads_param,  // [S,Q,3]
            const float* __restrict__ hr_param,     // [S]
            float* __restrict__ out) {
    extern __shared__ float sm[];
    float* buf[2];
    buf[0]       = sm;
    buf[1]       = sm + TILE * RSTRIDE;
    float* sm_h0 = sm + 2 * TILE * RSTRIDE;
    float* sm_h1 = sm_h0 + QB * 64;
    float* sm_h2 = sm_h1 + QB * 64;
    float* sm_hr = sm_h2 + QB * 64;
    float* sm_w  = sm_hr + SHEADS;
    __shared__ float  warpsum[2];
    __shared__ float  s_hrtmp[SHEADS];
    __shared__ float  s_hrsum;
    __shared__ int    s_nxt;          // block-uniform next ticket
    __shared__ int    s_last;         // last block to finish?
    __shared__ double red[NTHR];      // final-reduction scratch

    const int tid   = threadIdx.x;
    const int pg    = tid >> 6;       // 0..3: owns head pairs [pg*8, pg*8+8)
    const int wslot = tid & 63;       // words: wslot and wslot+64

    // ---- kick off prefetch of this block's first tile ----
    int cur = blockIdx.x;             // GRIDX <= NTILES, always valid here
    {
        const int rows = min(TILE, NWORDS - cur * TILE);
        const int n16  = rows * RSTRIDE / 4;          // rows multiple of 32
        const float* src = pauli + (size_t)cur * TILE * RSTRIDE;
        for (int i = tid; i < n16; i += NTHR)
            cp_async16(buf[0] + i * 4, src + i * 4);
        cp_commit();
    }

    // ---- head prep, once per block, overlapped with the cp.async in flight ----
    for (int i = tid; i < SHEADS * QB; i += NTHR) {
        const int s = i / QB;
        const int q = i - s * QB;
        const float* hp = heads_param + i * 3;        // i == s*QB + q
        float a = softplus20(hp[0]);
        float b = softplus20(hp[1]);
        float c = softplus20(hp[2]);
        float inv = 1.0f / fmaxf(a + b + c, 1e-12f);
        const int idx = q * 64 + (s >> 1) * 2 + (s & 1);
        sm_h0[idx] = a * inv;
        sm_h1[idx] = b * inv;
        sm_h2[idx] = c * inv;
    }
    if (tid < SHEADS) s_hrtmp[tid] = softplus20(hr_param[tid]);
    __syncthreads();
    if (tid < 32) {
        float v = s_hrtmp[tid] + s_hrtmp[tid + 32];
        #pragma unroll
        for (int off = 16; off; off >>= 1)
            v += __shfl_down_sync(0xffffffffu, v, off);
        if (tid == 0) s_hrsum = fmaxf(v, 1e-12f);
    }
    __syncthreads();
    if (tid < SHEADS)
        sm_hr[tid] = (s_hrtmp[tid] / s_hrsum + 0.001f / (float)SHEADS) / 1.001f;

    // block-uniform ticket fetch
    if (tid == 0) s_nxt = atomicAdd(&g_ticket, 1);

    int pb = 0;                       // buffer holding `cur`
    cp_wait_all();
    __syncthreads();                  // first tile + heads + hr + s_nxt ready

    while (cur < NTILES) {
        const int nxt = s_nxt;        // uniform (written before a prior barrier)

        // ---- prefetch the next tile into the other buffer ----
        if (nxt < NTILES) {
            const int rows_n = min(TILE, NWORDS - nxt * TILE);
            const int n16    = rows_n * RSTRIDE / 4;
            const float* src = pauli + (size_t)nxt * TILE * RSTRIDE;
            float* dst = buf[pb ^ 1];
            for (int i = tid; i < n16; i += NTHR)
                cp_async16(dst + i * 4, src + i * 4);
        }
        cp_commit();

        // ---- coverage: thread = (2 words: wslot, wslot+64) x (8 pairs of pg) ----
        const int rows = min(TILE, NWORDS - cur * TILE);
        const int w0 = wslot;
        const int w1 = wslot + 64;
        const float* r0 = buf[pb] + ((w0 < rows) ? w0 : 0) * RSTRIDE;
        const float* r1 = buf[pb] + ((w1 < rows) ? w1 : 0) * RSTRIDE;

        ull acc0[8], acc1[8];
        ull one; PACK2(one, 1.0f, 1.0f);
        #pragma unroll
        for (int i = 0; i < 8; ++i) { acc0[i] = one; acc1[i] = one; }

        const ulonglong2* H0 = (const ulonglong2*)sm_h0 + pg * 4;
        const ulonglong2* H1 = (const ulonglong2*)sm_h1 + pg * 4;
        const ulonglong2* H2 = (const ulonglong2*)sm_h2 + pg * 4;

        for (int q = 0; q < QB; ++q) {
            const float p00 = r0[q * 3 + 0];
            const float p01 = r0[q * 3 + 1];
            const float p02 = r0[q * 3 + 2];
            const float p10 = r1[q * 3 + 0];
            const float p11 = r1[q * 3 + 1];
            const float p12 = r1[q * 3 + 2];
            ull p00x, p01x, p02x, p10x, p11x, p12x;
            PACK2(p00x, p00, p00); PACK2(p01x, p01, p01); PACK2(p02x, p02, p02);
            PACK2(p10x, p10, p10); PACK2(p11x, p11, p11); PACK2(p12x, p12, p12);
            const ulonglong2* h0q = H0 + q * 16;   // 16 ulonglong2 per q per array
            const ulonglong2* h1q = H1 + q * 16;
            const ulonglong2* h2q = H2 + q * 16;
            #pragma unroll
            for (int j = 0; j < 4; ++j) {
                ulonglong2 a0 = h0q[j];   // broadcast LDS.128
                ulonglong2 a1 = h1q[j];
                ulonglong2 a2 = h2q[j];
                ull d;
                // word0, pairs 2j and 2j+1
                MUL2(d, p02x, a2.x);
                FMA2(d, p01x, a1.x, d);
                FMA2(d, p00x, a0.x, d);
                MUL2(acc0[2 * j + 0], acc0[2 * j + 0], d);
                MUL2(d, p02x, a2.y);
                FMA2(d, p01x, a1.y, d);
                FMA2(d, p00x, a0.y, d);
                MUL2(acc0[2 * j + 1], acc0[2 * j + 1], d);
                // word1, pairs 2j and 2j+1
                MUL2(d, p12x, a2.x);
                FMA2(d, p11x, a1.x, d);
                FMA2(d, p10x, a0.x, d);
                MUL2(acc1[2 * j + 0], acc1[2 * j + 0], d);
                MUL2(d, p12x, a2.y);
                FMA2(d, p11x, a1.y, d);
                FMA2(d, p10x, a0.y, d);
                MUL2(acc1[2 * j + 1], acc1[2 * j + 1], d);
            }
        }

        // ---- ratio-weighted sum over this pg's 16 heads, per word ----
        const ull* hrp = (const ull*)sm_hr + pg * 8;
        ull wa, wb; PACK2(wa, 0.0f, 0.0f); PACK2(wb, 0.0f, 0.0f);
        #pragma unroll
        for (int i = 0; i < 8; ++i) {
            FMA2(wa, hrp[i], acc0[i], wa);
            FMA2(wb, hrp[i], acc1[i], wb);
        }
        float lo, hi;
        UNPACK2(lo, hi, wa); const float part0 = lo + hi;
        UNPACK2(lo, hi, wb); const float part1 = lo + hi;

        if (pg) {
            sm_w[(pg - 1) * TILE + w0] = part0;
            sm_w[(pg - 1) * TILE + w1] = part1;
        }
        __syncthreads();                 // B1: partials ready; separates s_nxt

        if (tid == 0 && nxt < NTILES) s_nxt = atomicAdd(&g_ticket, 1);

        float term = 0.0f;
        if (pg == 0) {
            if (w0 < rows) {
                const float c = coeff[cur * TILE + w0];
                const float cov = part0 + sm_w[w0] + sm_w[TILE + w0] + sm_w[2 * TILE + w0];
                term = (c * c) / cov;
            }
            if (w1 < rows) {
                const float c = coeff[cur * TILE + w1];
                const float cov = part1 + sm_w[w1] + sm_w[TILE + w1] + sm_w[2 * TILE + w1];
                term += (c * c) / cov;
            }
        }
        // deterministic reduction: nonzero terms live in warps 0-1 (tid<64)
        #pragma unroll
        for (int off = 16; off; off >>= 1)
            term += __shfl_down_sync(0xffffffffu, term, off);
        if (tid < 64 && (tid & 31) == 0) warpsum[tid >> 5] = term;
        __syncthreads();
        if (tid == 0) g_part[cur] = (double)warpsum[0] + (double)warpsum[1];

        cp_wait_all();
        __syncthreads();                 // B2: buffer ready, smem reusable
        cur = nxt;
        pb ^= 1;
    }

    // ---- fused final reduction: last block to finish sums g_part ----
    if (tid == 0) {
        __threadfence();                              // publish g_part writes
        s_last = (atomicAdd(&g_done, 1) == GRIDX - 1);
    }
    __syncthreads();
    if (s_last) {
        __threadfence();                              // acquire g_part writes
        double v = 0.0;
        #pragma unroll
        for (int k = 0; k < (NTILES + NTHR - 1) / NTHR; ++k) {
            int idx = tid + k * NTHR;
            if (idx < NTILES) v += g_part[idx];
        }
        red[tid] = v;
        __syncthreads();
        #pragma unroll
        for (int off = NTHR / 2; off; off >>= 1) {
            if (tid < off) red[tid] += red[tid + off];
            __syncthreads();
        }
        if (tid == 0) {
            out[0] = (float)red[0];
            g_ticket = GRIDX;   // reset scheduler state for the next replay
            g_done   = 0;
        }
    }
}

extern "C" void kernel_launch(void* const* d_in, const int* in_sizes, int n_in,
                              void* d_out, int out_size) {
    const float* pauli = (const float*)d_in[0];  // [N,Q,P]
    const float* coeff = (const float*)d_in[1];  // [N]
    const float* hp    = (const float*)d_in[2];  // [S,Q,P]
    const float* hrp   = (const float*)d_in[3];  // [S]
    float* out = (float*)d_out;

    const size_t smem = (size_t)SMEM_FLOATS * sizeof(float); // 193792 B
    cudaFuncSetAttribute(main_kernel, cudaFuncAttributeMaxDynamicSharedMemorySize, (int)smem);

    main_kernel<<<GRIDX, NTHR, smem>>>(pauli, coeff, hp, hrp, out);
}